// round 1
// baseline (speedup 1.0000x reference)
#include <cuda_runtime.h>
#include <math.h>

// Problem constants
#define Bc   2
#define Sc   2048
#define HIDc 2048
#define Hc   16
#define HKVc 4
#define Dc   128
#define BSc  64
#define NBc  32
#define SCALEc 0.08838834764831845f   // 1/sqrt(128)

// ---------------- scratch (device globals; no allocation allowed) ----------------
__device__ float    g_qkv[(size_t)4096 * 3072];          // hidden @ [Wq|Wk|Wv]
__device__ float    g_q  [(size_t)Bc * Hc   * Sc * Dc];  // roped, (B,H,S,D)
__device__ float    g_k  [(size_t)Bc * HKVc * Sc * Dc];  // roped, (B,HKV,S,D)
__device__ float    g_v  [(size_t)Bc * HKVc * Sc * Dc];
__device__ float    g_qblk[Bc * Hc   * NBc * Dc];
__device__ float    g_kblk[Bc * HKVc * NBc * Dc];
__device__ unsigned g_mask[Bc * Hc * NBc];               // bit j of row i: block (i,j) active
__device__ float    g_attn[(size_t)4096 * 2048];         // (B,S,H*D)

// ---------------- 128x128x8 fp32 SGEMM body ----------------
__device__ __forceinline__ void sgemm_body(
    const float* __restrict__ A, int lda,
    const float* __restrict__ Bt, int ldb,   // already offset to this block's col 0
    float* __restrict__ C, int ldc,          // already offset to this block's col 0
    int K, int row0)
{
    __shared__ float As[8][128];
    __shared__ float Bs[8][128];
    const int tid = threadIdx.x;
    const int ty = tid >> 4, tx = tid & 15;

    float acc[8][8];
#pragma unroll
    for (int i = 0; i < 8; i++)
#pragma unroll
        for (int j = 0; j < 8; j++) acc[i][j] = 0.f;

    const int aRow = tid >> 1, aCol = (tid & 1) * 4;
    const int bRow = tid >> 5, bCol = (tid & 31) * 4;
    const float* Ap = A + (size_t)(row0 + aRow) * lda + aCol;
    const float* Bp = Bt + (size_t)bRow * ldb + bCol;

    for (int k0 = 0; k0 < K; k0 += 8) {
        float4 av = *(const float4*)(Ap + k0);
        float4 bv = *(const float4*)(Bp + (size_t)k0 * ldb);
        As[aCol + 0][aRow] = av.x;
        As[aCol + 1][aRow] = av.y;
        As[aCol + 2][aRow] = av.z;
        As[aCol + 3][aRow] = av.w;
        *(float4*)&Bs[bRow][bCol] = bv;
        __syncthreads();
#pragma unroll
        for (int kk = 0; kk < 8; kk++) {
            float a[8], b[8];
            *(float4*)(a)     = *(const float4*)&As[kk][ty * 8];
            *(float4*)(a + 4) = *(const float4*)&As[kk][ty * 8 + 4];
            *(float4*)(b)     = *(const float4*)&Bs[kk][tx * 8];
            *(float4*)(b + 4) = *(const float4*)&Bs[kk][tx * 8 + 4];
#pragma unroll
            for (int i = 0; i < 8; i++)
#pragma unroll
                for (int j = 0; j < 8; j++)
                    acc[i][j] = fmaf(a[i], b[j], acc[i][j]);
        }
        __syncthreads();
    }

#pragma unroll
    for (int i = 0; i < 8; i++) {
        float* cp = C + (size_t)(row0 + ty * 8 + i) * ldc + tx * 8;
        *(float4*)(cp)     = make_float4(acc[i][0], acc[i][1], acc[i][2], acc[i][3]);
        *(float4*)(cp + 4) = make_float4(acc[i][4], acc[i][5], acc[i][6], acc[i][7]);
    }
}

// QKV fused GEMM: N=3072 = [2048 q | 512 k | 512 v]; tiles never cross boundaries.
__global__ __launch_bounds__(256) void sgemm_qkv(
    const float* __restrict__ A,
    const float* __restrict__ Wq, const float* __restrict__ Wk, const float* __restrict__ Wv,
    float* __restrict__ C)
{
    int col0 = blockIdx.x * 128;
    const float* Bm; int ldb; int c;
    if (col0 < 2048)      { Bm = Wq; ldb = 2048; c = col0; }
    else if (col0 < 2560) { Bm = Wk; ldb = 512;  c = col0 - 2048; }
    else                  { Bm = Wv; ldb = 512;  c = col0 - 2560; }
    sgemm_body(A, HIDc, Bm + c, ldb, C + col0, 3072, HIDc, blockIdx.y * 128);
}

__global__ __launch_bounds__(256) void sgemm_plain(
    const float* __restrict__ A, int lda,
    const float* __restrict__ Bm, int ldb,
    float* __restrict__ C, int ldc, int K)
{
    int col0 = blockIdx.x * 128;
    sgemm_body(A, lda, Bm + col0, ldb, C + col0, ldc, K, blockIdx.y * 128);
}

// ---------------- RoPE + reshape: qkv(B,S,3072) -> q(B,H,S,D), k/v(B,HKV,S,D) ----------------
__global__ void rope_kernel(const float* __restrict__ qkv,
                            const float* __restrict__ cosb,
                            const float* __restrict__ sinb)
{
    int s = blockIdx.x, b = blockIdx.y;
    const float* row = qkv + (size_t)(b * Sc + s) * 3072;
    const float* cr  = cosb + (size_t)(b * Sc + s) * Dc;
    const float* sr  = sinb + (size_t)(b * Sc + s) * Dc;
    int t = threadIdx.x;

    for (int p = t; p < Hc * 64; p += 256) {            // q pairs
        int h = p >> 6, d = p & 63;
        float x1 = row[h * 128 + d], x2 = row[h * 128 + d + 64];
        float* out = g_q + ((size_t)(b * Hc + h) * Sc + s) * Dc;
        out[d]      = x1 * cr[d]      - x2 * sr[d];
        out[d + 64] = x2 * cr[d + 64] + x1 * sr[d + 64];
    }
    for (int p = t; p < HKVc * 64; p += 256) {          // k pairs
        int h = p >> 6, d = p & 63;
        float x1 = row[2048 + h * 128 + d], x2 = row[2048 + h * 128 + d + 64];
        float* out = g_k + ((size_t)(b * HKVc + h) * Sc + s) * Dc;
        out[d]      = x1 * cr[d]      - x2 * sr[d];
        out[d + 64] = x2 * cr[d + 64] + x1 * sr[d + 64];
    }
    for (int p = t; p < HKVc * Dc; p += 256) {          // v copy
        int h = p >> 7, d = p & 127;
        g_v[((size_t)(b * HKVc + h) * Sc + s) * Dc + d] = row[2560 + h * 128 + d];
    }
}

// ---------------- block means over BS=64 rows ----------------
__global__ void blockmean_kernel(const float* __restrict__ x, float* __restrict__ out, int HH)
{
    int i = blockIdx.x, h = blockIdx.y, b = blockIdx.z, d = threadIdx.x;
    const float* base = x + ((size_t)(b * HH + h) * Sc + i * BSc) * Dc + d;
    float sum = 0.f;
#pragma unroll
    for (int r = 0; r < BSc; r++) sum += base[(size_t)r * Dc];
    out[((size_t)(b * HH + h) * NBc + i) * Dc + d] = sum * (1.0f / 64.0f);
}

// ---------------- gate mask: sigmoid(logit)>=0.5 <=> logit>=0; pack row bitmask ----------------
__global__ __launch_bounds__(1024) void mask_kernel()
{
    int bh = blockIdx.x;                 // b*H + h
    int b = bh / Hc, h = bh % Hc;
    int t = threadIdx.x;
    int i = t >> 5, j = t & 31;
    const float* qb = g_qblk + ((size_t)bh * NBc + i) * Dc;
    const float* kb = g_kblk + ((size_t)(b * HKVc + (h >> 2)) * NBc + j) * Dc;
    float dot = 0.f;
#pragma unroll 8
    for (int d = 0; d < Dc; d++) dot = fmaf(qb[d], kb[d], dot);
    bool hard = (dot * SCALEc >= 0.0f) || (i == j);
    hard = hard && (j <= i);
    unsigned bits = __ballot_sync(0xffffffffu, hard);
    if (j == 0) g_mask[(size_t)bh * NBc + i] = bits;
}

// ---------------- block-sparse flash attention ----------------
// CTA = (query block ib, head h, batch b). 256 threads, 4x4 score tile / 4x8 out tile.
#define QP 129   // K/Q smem row stride (odd -> conflict-free scalar reads across lanes)
#define PP 65    // P smem row stride
__global__ __launch_bounds__(256) void flash_kernel()
{
    extern __shared__ float sm[];
    float* Qs = sm;                 // [64][QP]
    float* Ks = Qs + 64 * QP;       // [64][QP]; aliased as Vs [64][128]
    float* Ps = Ks + 64 * QP;       // [64][PP]
    float* Vs = Ks;

    int ib = blockIdx.x, h = blockIdx.y, b = blockIdx.z;
    int t = threadIdx.x;
    int ty = t >> 4, tx = t & 15;

    const float* qg = g_q + ((size_t)(b * Hc + h) * Sc + ib * 64) * Dc;
    const float* kg = g_k + ((size_t)(b * HKVc + (h >> 2)) * Sc) * Dc;
    const float* vg = g_v + ((size_t)(b * HKVc + (h >> 2)) * Sc) * Dc;
    const unsigned maskrow = g_mask[(size_t)(b * Hc + h) * NBc + ib];

    // load Q tile (64 x 128) into padded smem
    for (int idx = t * 4; idx < 64 * 128; idx += 1024) {
        int r = idx >> 7, c = idx & 127;
        float4 v4 = *(const float4*)(qg + r * Dc + c);
        float* dst = Qs + r * QP + c;
        dst[0] = v4.x; dst[1] = v4.y; dst[2] = v4.z; dst[3] = v4.w;
    }

    float m[4], l[4], acc[4][8];
#pragma unroll
    for (int i = 0; i < 4; i++) {
        m[i] = -1e38f; l[i] = 0.f;
#pragma unroll
        for (int j = 0; j < 8; j++) acc[i][j] = 0.f;
    }
    __syncthreads();

    for (int jb = 0; jb <= ib; jb++) {
        if (!((maskrow >> jb) & 1u)) continue;
        const bool diag = (jb == ib);

        // ---- load K block (transpose-free, padded rows) ----
        const float* kp = kg + (size_t)jb * 64 * Dc;
        for (int idx = t * 4; idx < 64 * 128; idx += 1024) {
            int r = idx >> 7, c = idx & 127;
            float4 v4 = *(const float4*)(kp + r * Dc + c);
            float* dst = Ks + r * QP + c;
            dst[0] = v4.x; dst[1] = v4.y; dst[2] = v4.z; dst[3] = v4.w;
        }
        __syncthreads();

        // ---- scores: s[i][j] = q(row ty*4+i) . k(col tx*4+j) ----
        float s[4][4];
#pragma unroll
        for (int i = 0; i < 4; i++)
#pragma unroll
            for (int j = 0; j < 4; j++) s[i][j] = 0.f;
#pragma unroll 4
        for (int d = 0; d < Dc; d++) {
            float a[4], bb[4];
#pragma unroll
            for (int i = 0; i < 4; i++) a[i]  = Qs[(ty * 4 + i) * QP + d];
#pragma unroll
            for (int j = 0; j < 4; j++) bb[j] = Ks[(tx * 4 + j) * QP + d];
#pragma unroll
            for (int i = 0; i < 4; i++)
#pragma unroll
                for (int j = 0; j < 4; j++)
                    s[i][j] = fmaf(a[i], bb[j], s[i][j]);
        }

        // ---- online softmax (rows split across 16 lanes; reduce via shfl) ----
#pragma unroll
        for (int i = 0; i < 4; i++) {
            int r = ty * 4 + i;
            float sv[4];
            float mb = -1e38f;
#pragma unroll
            for (int j = 0; j < 4; j++) {
                float v = s[i][j] * SCALEc;
                if (diag && (tx * 4 + j) > r) v = -1e30f;
                sv[j] = v;
                mb = fmaxf(mb, v);
            }
#pragma unroll
            for (int o = 1; o < 16; o <<= 1)
                mb = fmaxf(mb, __shfl_xor_sync(0xffffffffu, mb, o));
            float mn = fmaxf(m[i], mb);
            float alpha = __expf(m[i] - mn);
            m[i] = mn;
            float ls = 0.f;
#pragma unroll
            for (int j = 0; j < 4; j++) {
                float p = __expf(sv[j] - mn);
                Ps[r * PP + tx * 4 + j] = p;
                ls += p;
            }
#pragma unroll
            for (int o = 1; o < 16; o <<= 1)
                ls += __shfl_xor_sync(0xffffffffu, ls, o);
            l[i] = l[i] * alpha + ls;
#pragma unroll
            for (int jj = 0; jj < 8; jj++) acc[i][jj] *= alpha;
        }
        __syncthreads();   // K reads done + P visible

        // ---- load V block into the K buffer (natural [64][128]) ----
        const float* vp = vg + (size_t)jb * 64 * Dc;
        for (int idx = t * 4; idx < 64 * 128; idx += 1024) {
            int r = idx >> 7, c = idx & 127;
            *(float4*)(Vs + r * 128 + c) = *(const float4*)(vp + r * Dc + c);
        }
        __syncthreads();

        // ---- acc += P @ V  (rows ty*4+i, cols tx*8..tx*8+7) ----
#pragma unroll 2
        for (int c = 0; c < 64; c++) {
            float pv[4];
#pragma unroll
            for (int i = 0; i < 4; i++) pv[i] = Ps[(ty * 4 + i) * PP + c];
            float4 v0 = *(const float4*)(Vs + c * 128 + tx * 8);
            float4 v1 = *(const float4*)(Vs + c * 128 + tx * 8 + 4);
#pragma unroll
            for (int i = 0; i < 4; i++) {
                acc[i][0] = fmaf(pv[i], v0.x, acc[i][0]);
                acc[i][1] = fmaf(pv[i], v0.y, acc[i][1]);
                acc[i][2] = fmaf(pv[i], v0.z, acc[i][2]);
                acc[i][3] = fmaf(pv[i], v0.w, acc[i][3]);
                acc[i][4] = fmaf(pv[i], v1.x, acc[i][4]);
                acc[i][5] = fmaf(pv[i], v1.y, acc[i][5]);
                acc[i][6] = fmaf(pv[i], v1.z, acc[i][6]);
                acc[i][7] = fmaf(pv[i], v1.w, acc[i][7]);
            }
        }
        __syncthreads();   // V/P reads done before next iteration's stores
    }

    // ---- epilogue: normalize + write (B,S,H*D) ----
#pragma unroll
    for (int i = 0; i < 4; i++) {
        float inv = 1.0f / l[i];
        size_t row = (size_t)b * Sc + ib * 64 + ty * 4 + i;
        float* op = g_attn + row * 2048 + h * 128 + tx * 8;
        *(float4*)(op)     = make_float4(acc[i][0] * inv, acc[i][1] * inv,
                                         acc[i][2] * inv, acc[i][3] * inv);
        *(float4*)(op + 4) = make_float4(acc[i][4] * inv, acc[i][5] * inv,
                                         acc[i][6] * inv, acc[i][7] * inv);
    }
}

// ---------------- launch ----------------
extern "C" void kernel_launch(void* const* d_in, const int* in_sizes, int n_in,
                              void* d_out, int out_size)
{
    const float* hidden = (const float*)d_in[0];
    const float* cosb   = (const float*)d_in[1];
    const float* sinb   = (const float*)d_in[2];
    const float* Wq     = (const float*)d_in[3];
    const float* Wk     = (const float*)d_in[4];
    const float* Wv     = (const float*)d_in[5];
    const float* Wo     = (const float*)d_in[6];
    float* out = (float*)d_out;

    float *qkv, *q, *k, *qblk, *kblk, *attn;
    cudaGetSymbolAddress((void**)&qkv,  g_qkv);
    cudaGetSymbolAddress((void**)&q,    g_q);
    cudaGetSymbolAddress((void**)&k,    g_k);
    cudaGetSymbolAddress((void**)&qblk, g_qblk);
    cudaGetSymbolAddress((void**)&kblk, g_kblk);
    cudaGetSymbolAddress((void**)&attn, g_attn);

    // 1. fused QKV projection: (4096 x 2048) @ (2048 x 3072)
    sgemm_qkv<<<dim3(3072 / 128, 4096 / 128), 256>>>(hidden, Wq, Wk, Wv, qkv);

    // 2. RoPE + layout change
    rope_kernel<<<dim3(Sc, Bc), 256>>>(qkv, cosb, sinb);

    // 3. block means
    blockmean_kernel<<<dim3(NBc, Hc,   Bc), 128>>>(q, qblk, Hc);
    blockmean_kernel<<<dim3(NBc, HKVc, Bc), 128>>>(k, kblk, HKVc);

    // 4. gate bitmask
    mask_kernel<<<Bc * Hc, 1024>>>();

    // 5. block-sparse flash attention
    int smem = (64 * QP * 2 + 64 * PP) * (int)sizeof(float);   // 82688 B
    cudaFuncSetAttribute(flash_kernel, cudaFuncAttributeMaxDynamicSharedMemorySize, smem);
    flash_kernel<<<dim3(NBc, Hc, Bc), 256, smem>>>();

    // 6. output projection: (4096 x 2048) @ (2048 x 2048)
    sgemm_plain<<<dim3(2048 / 128, 4096 / 128), 256>>>(attn, 2048, Wo, 2048, out, 2048, 2048);
}

// round 4
// speedup vs baseline: 1.2683x; 1.2683x over previous
#include <cuda_runtime.h>
#include <math.h>
#include <cstdint>

// Problem constants
#define Bc   2
#define Sc   2048
#define HIDc 2048
#define Hc   16
#define HKVc 4
#define Dc   128
#define BSc  64
#define NBc  32
#define SCALEc 0.08838834764831845f   // 1/sqrt(128)

// ---------------- scratch (device globals; no allocation allowed) ----------------
__device__ float    g_qkv[(size_t)4096 * 3072];          // hidden @ [Wq|Wk|Wv]
__device__ float    g_q  [(size_t)Bc * Hc   * Sc * Dc];  // roped, (B,H,S,D)
__device__ float    g_k  [(size_t)Bc * HKVc * Sc * Dc];  // roped, (B,HKV,S,D)
__device__ float    g_v  [(size_t)Bc * HKVc * Sc * Dc];
__device__ float    g_qblk[Bc * Hc   * NBc * Dc];
__device__ float    g_kblk[Bc * HKVc * NBc * Dc];
__device__ unsigned g_mask[Bc * Hc * NBc];               // bit j of row i: block (i,j) active
__device__ float    g_attn[(size_t)4096 * 2048];         // (B,S,H*D)
__device__ float    g_wt [(size_t)3072 * 2048];          // [Wq^T ; Wk^T ; Wv^T]  rows=N, cols=K
__device__ float    g_wot[(size_t)2048 * 2048];          // Wo^T

// ======================= helpers =======================
__device__ __forceinline__ uint32_t f2tf32(float x) {
    uint32_t u;
    asm("cvt.rna.tf32.f32 %0, %1;" : "=r"(u) : "f"(x));
    return u;
}

// mma.sync m16n8k8 tf32: D += A*B  (A row-major 16x8, B col-major 8x8)
#define MMA_TF32(d, a, b) \
    asm volatile("mma.sync.aligned.m16n8k8.row.col.f32.tf32.tf32.f32 " \
        "{%0,%1,%2,%3}, {%4,%5,%6,%7}, {%8,%9}, {%0,%1,%2,%3};" \
        : "+f"((d)[0]), "+f"((d)[1]), "+f"((d)[2]), "+f"((d)[3]) \
        : "r"((a)[0]), "r"((a)[1]), "r"((a)[2]), "r"((a)[3]), \
          "r"((b)[0]), "r"((b)[1]))

// ================== mma.sync tf32 3xTF32 GEMM: C[M,*] = A[M,K] @ Bt[N,K]^T ==================
// CTA tile 128x128, K-chunk 16. smem per stage: Ah | Al | Bh | Bl, each 128 x 20 floats
// (stride 20: (20*g + k) mod 32 is a permutation over g=0..7,k=0..3 -> conflict-free frags).
#define KC       16
#define TSTRIDE  20                       // floats per row
#define TILE_F   (128 * TSTRIDE)          // 2560 floats / tile
#define STAGE_F  (4 * TILE_F)             // Ah Al Bh Bl
#define GEMM_SMEM (2 * STAGE_F * (int)sizeof(float))   // 81920 B

__global__ void __launch_bounds__(256, 2) gemm_mma(
    const float* __restrict__ A, const float* __restrict__ Bt,
    float* __restrict__ C, int ldc, int K)
{
    extern __shared__ float sm[];
    const int tid = threadIdx.x;
    const int wid = tid >> 5, lane = tid & 31;
    const int wm = wid & 1, wn = wid >> 1;        // warp grid 2(m) x 4(n), warp tile 64x32
    const int g = lane >> 2, q = lane & 3;
    const int row0 = blockIdx.y * 128;
    const int col0 = blockIdx.x * 128;
    const float* Ab = A  + (size_t)row0 * K;
    const float* Bb = Bt + (size_t)col0 * K;

    float acc[4][4][4];
#pragma unroll
    for (int t = 0; t < 4; t++)
#pragma unroll
        for (int u = 0; u < 4; u++)
#pragma unroll
            for (int r = 0; r < 4; r++) acc[t][u][r] = 0.f;

    // Per-thread fill slots: i = tid, tid+256 over 512 float4 per operand tile.
    const int fr0 = tid >> 2,        fc0 = (tid & 3) * 4;          // row, col(float)
    const int fr1 = (tid + 256) >> 2, fc1 = ((tid + 256) & 3) * 4;

    float4 pa0, pa1, pb0, pb1;   // pending gmem loads for next chunk

    auto ldnext = [&](int kc) {
        const int k0 = kc * KC;
        pa0 = *(const float4*)(Ab + (size_t)fr0 * K + k0 + fc0);
        pa1 = *(const float4*)(Ab + (size_t)fr1 * K + k0 + fc1);
        pb0 = *(const float4*)(Bb + (size_t)fr0 * K + k0 + fc0);
        pb1 = *(const float4*)(Bb + (size_t)fr1 * K + k0 + fc1);
    };

    auto cvt_store = [&](float* st) {
        float* AH = st;           float* AL = st + TILE_F;
        float* BH = st + 2 * TILE_F; float* BL = st + 3 * TILE_F;
        float av[8] = {pa0.x, pa0.y, pa0.z, pa0.w, pa1.x, pa1.y, pa1.z, pa1.w};
        float bv[8] = {pb0.x, pb0.y, pb0.z, pb0.w, pb1.x, pb1.y, pb1.z, pb1.w};
        uint4 h, l;
        int off0 = fr0 * TSTRIDE + fc0, off1 = fr1 * TSTRIDE + fc1;
        h.x = f2tf32(av[0]); l.x = f2tf32(av[0] - __uint_as_float(h.x));
        h.y = f2tf32(av[1]); l.y = f2tf32(av[1] - __uint_as_float(h.y));
        h.z = f2tf32(av[2]); l.z = f2tf32(av[2] - __uint_as_float(h.z));
        h.w = f2tf32(av[3]); l.w = f2tf32(av[3] - __uint_as_float(h.w));
        *(uint4*)(AH + off0) = h; *(uint4*)(AL + off0) = l;
        h.x = f2tf32(av[4]); l.x = f2tf32(av[4] - __uint_as_float(h.x));
        h.y = f2tf32(av[5]); l.y = f2tf32(av[5] - __uint_as_float(h.y));
        h.z = f2tf32(av[6]); l.z = f2tf32(av[6] - __uint_as_float(h.z));
        h.w = f2tf32(av[7]); l.w = f2tf32(av[7] - __uint_as_float(h.w));
        *(uint4*)(AH + off1) = h; *(uint4*)(AL + off1) = l;
        h.x = f2tf32(bv[0]); l.x = f2tf32(bv[0] - __uint_as_float(h.x));
        h.y = f2tf32(bv[1]); l.y = f2tf32(bv[1] - __uint_as_float(h.y));
        h.z = f2tf32(bv[2]); l.z = f2tf32(bv[2] - __uint_as_float(h.z));
        h.w = f2tf32(bv[3]); l.w = f2tf32(bv[3] - __uint_as_float(h.w));
        *(uint4*)(BH + off0) = h; *(uint4*)(BL + off0) = l;
        h.x = f2tf32(bv[4]); l.x = f2tf32(bv[4] - __uint_as_float(h.x));
        h.y = f2tf32(bv[5]); l.y = f2tf32(bv[5] - __uint_as_float(h.y));
        h.z = f2tf32(bv[6]); l.z = f2tf32(bv[6] - __uint_as_float(h.z));
        h.w = f2tf32(bv[7]); l.w = f2tf32(bv[7] - __uint_as_float(h.w));
        *(uint4*)(BH + off1) = h; *(uint4*)(BL + off1) = l;
    };

    auto compute = [&](int s) {
        const float* st = sm + s * STAGE_F;
        const float* AH = st;             const float* AL = st + TILE_F;
        const float* BH = st + 2 * TILE_F; const float* BL = st + 3 * TILE_F;
#pragma unroll
        for (int k8 = 0; k8 < 2; k8++) {
            const int kq = k8 * 8 + q;
            uint32_t ah[4][4], al[4][4], bh[4][2], bl[4][2];
#pragma unroll
            for (int t = 0; t < 4; t++) {
                int r = wm * 64 + t * 16 + g;
                ah[t][0] = __float_as_uint(AH[r * TSTRIDE + kq]);
                ah[t][1] = __float_as_uint(AH[(r + 8) * TSTRIDE + kq]);
                ah[t][2] = __float_as_uint(AH[r * TSTRIDE + kq + 4]);
                ah[t][3] = __float_as_uint(AH[(r + 8) * TSTRIDE + kq + 4]);
                al[t][0] = __float_as_uint(AL[r * TSTRIDE + kq]);
                al[t][1] = __float_as_uint(AL[(r + 8) * TSTRIDE + kq]);
                al[t][2] = __float_as_uint(AL[r * TSTRIDE + kq + 4]);
                al[t][3] = __float_as_uint(AL[(r + 8) * TSTRIDE + kq + 4]);
            }
#pragma unroll
            for (int u = 0; u < 4; u++) {
                int n = wn * 32 + u * 8 + g;
                bh[u][0] = __float_as_uint(BH[n * TSTRIDE + kq]);
                bh[u][1] = __float_as_uint(BH[n * TSTRIDE + kq + 4]);
                bl[u][0] = __float_as_uint(BL[n * TSTRIDE + kq]);
                bl[u][1] = __float_as_uint(BL[n * TSTRIDE + kq + 4]);
            }
#pragma unroll
            for (int t = 0; t < 4; t++)
#pragma unroll
                for (int u = 0; u < 4; u++) {
                    MMA_TF32(acc[t][u], ah[t], bh[u]);
                    MMA_TF32(acc[t][u], ah[t], bl[u]);
                    MMA_TF32(acc[t][u], al[t], bh[u]);
                }
        }
    };

    const int nch = K / KC;
    ldnext(0); cvt_store(sm);
    __syncthreads();
    for (int kc = 0; kc < nch; kc++) {
        int s = kc & 1;
        if (kc + 1 < nch) ldnext(kc + 1);
        compute(s);
        if (kc + 1 < nch) cvt_store(sm + (s ^ 1) * STAGE_F);
        __syncthreads();
    }

    // epilogue: regs -> C
#pragma unroll
    for (int t = 0; t < 4; t++) {
        int r = row0 + wm * 64 + t * 16 + g;
#pragma unroll
        for (int u = 0; u < 4; u++) {
            int c = col0 + wn * 32 + u * 8 + q * 2;
            *(float2*)(C + (size_t)r * ldc + c)       = make_float2(acc[t][u][0], acc[t][u][1]);
            *(float2*)(C + (size_t)(r + 8) * ldc + c) = make_float2(acc[t][u][2], acc[t][u][3]);
        }
    }
}

// ---------------- weight transpose: in[Kdim][Ndim] -> out[Ndim][Kdim] ----------------
__global__ __launch_bounds__(256) void transpose_k(
    const float* __restrict__ in, float* __restrict__ out, int Kdim, int Ndim)
{
    __shared__ float t[32][33];
    int bx = blockIdx.x * 32, by = blockIdx.y * 32;   // bx: n, by: k
    int x = threadIdx.x, y = threadIdx.y;             // 32 x 8
#pragma unroll
    for (int i = 0; i < 32; i += 8)
        t[y + i][x] = in[(size_t)(by + y + i) * Ndim + bx + x];
    __syncthreads();
#pragma unroll
    for (int i = 0; i < 32; i += 8)
        out[(size_t)(bx + y + i) * Kdim + by + x] = t[x][y + i];
}

// ---------------- RoPE + reshape: qkv(B,S,3072) -> q(B,H,S,D), k/v(B,HKV,S,D) ----------------
__global__ void rope_kernel(const float* __restrict__ qkv,
                            const float* __restrict__ cosb,
                            const float* __restrict__ sinb)
{
    int s = blockIdx.x, b = blockIdx.y;
    const float* row = qkv + (size_t)(b * Sc + s) * 3072;
    const float* cr  = cosb + (size_t)(b * Sc + s) * Dc;
    const float* sr  = sinb + (size_t)(b * Sc + s) * Dc;
    int t = threadIdx.x;

    for (int p = t; p < Hc * 64; p += 256) {            // q pairs
        int h = p >> 6, d = p & 63;
        float x1 = row[h * 128 + d], x2 = row[h * 128 + d + 64];
        float* out = g_q + ((size_t)(b * Hc + h) * Sc + s) * Dc;
        out[d]      = x1 * cr[d]      - x2 * sr[d];
        out[d + 64] = x2 * cr[d + 64] + x1 * sr[d + 64];
    }
    for (int p = t; p < HKVc * 64; p += 256) {          // k pairs
        int h = p >> 6, d = p & 63;
        float x1 = row[2048 + h * 128 + d], x2 = row[2048 + h * 128 + d + 64];
        float* out = g_k + ((size_t)(b * HKVc + h) * Sc + s) * Dc;
        out[d]      = x1 * cr[d]      - x2 * sr[d];
        out[d + 64] = x2 * cr[d + 64] + x1 * sr[d + 64];
    }
    for (int p = t; p < HKVc * Dc; p += 256) {          // v copy
        int h = p >> 7, d = p & 127;
        g_v[((size_t)(b * HKVc + h) * Sc + s) * Dc + d] = row[2560 + h * 128 + d];
    }
}

// ---------------- block means over BS=64 rows ----------------
__global__ void blockmean_kernel(const float* __restrict__ x, float* __restrict__ out, int HH)
{
    int i = blockIdx.x, h = blockIdx.y, b = blockIdx.z, d = threadIdx.x;
    const float* base = x + ((size_t)(b * HH + h) * Sc + i * BSc) * Dc + d;
    float sum = 0.f;
#pragma unroll
    for (int r = 0; r < BSc; r++) sum += base[(size_t)r * Dc];
    out[((size_t)(b * HH + h) * NBc + i) * Dc + d] = sum * (1.0f / 64.0f);
}

// ---------------- gate mask: sigmoid(logit)>=0.5 <=> logit>=0; pack row bitmask ----------------
__global__ __launch_bounds__(1024) void mask_kernel()
{
    int bh = blockIdx.x;                 // b*H + h
    int b = bh / Hc, h = bh % Hc;
    int t = threadIdx.x;
    int i = t >> 5, j = t & 31;
    const float* qb = g_qblk + ((size_t)bh * NBc + i) * Dc;
    const float* kb = g_kblk + ((size_t)(b * HKVc + (h >> 2)) * NBc + j) * Dc;
    float dot = 0.f;
#pragma unroll 8
    for (int d = 0; d < Dc; d++) dot = fmaf(qb[d], kb[d], dot);
    bool hard = (dot * SCALEc >= 0.0f) || (i == j);
    hard = hard && (j <= i);
    unsigned bits = __ballot_sync(0xffffffffu, hard);
    if (j == 0) g_mask[(size_t)bh * NBc + i] = bits;
}

// ---------------- block-sparse flash attention (fp32) ----------------
#define QP 129   // K/Q smem row stride
#define PP 65    // P smem row stride
__global__ __launch_bounds__(256) void flash_kernel()
{
    extern __shared__ float smf[];
    float* Qs = smf;                // [64][QP]
    float* Ks = Qs + 64 * QP;       // [64][QP]; aliased as Vs [64][128]
    float* Ps = Ks + 64 * QP;       // [64][PP]
    float* Vs = Ks;

    int ib = blockIdx.x, h = blockIdx.y, b = blockIdx.z;
    int t = threadIdx.x;
    int ty = t >> 4, tx = t & 15;

    const float* qg = g_q + ((size_t)(b * Hc + h) * Sc + ib * 64) * Dc;
    const float* kg = g_k + ((size_t)(b * HKVc + (h >> 2)) * Sc) * Dc;
    const float* vg = g_v + ((size_t)(b * HKVc + (h >> 2)) * Sc) * Dc;
    const unsigned maskrow = g_mask[(size_t)(b * Hc + h) * NBc + ib];

    for (int idx = t * 4; idx < 64 * 128; idx += 1024) {
        int r = idx >> 7, c = idx & 127;
        float4 v4 = *(const float4*)(qg + r * Dc + c);
        float* dst = Qs + r * QP + c;
        dst[0] = v4.x; dst[1] = v4.y; dst[2] = v4.z; dst[3] = v4.w;
    }

    float m[4], l[4], acc[4][8];
#pragma unroll
    for (int i = 0; i < 4; i++) {
        m[i] = -1e38f; l[i] = 0.f;
#pragma unroll
        for (int j = 0; j < 8; j++) acc[i][j] = 0.f;
    }
    __syncthreads();

    for (int jb = 0; jb <= ib; jb++) {
        if (!((maskrow >> jb) & 1u)) continue;
        const bool diag = (jb == ib);

        const float* kp = kg + (size_t)jb * 64 * Dc;
        for (int idx = t * 4; idx < 64 * 128; idx += 1024) {
            int r = idx >> 7, c = idx & 127;
            float4 v4 = *(const float4*)(kp + r * Dc + c);
            float* dst = Ks + r * QP + c;
            dst[0] = v4.x; dst[1] = v4.y; dst[2] = v4.z; dst[3] = v4.w;
        }
        __syncthreads();

        float s[4][4];
#pragma unroll
        for (int i = 0; i < 4; i++)
#pragma unroll
            for (int j = 0; j < 4; j++) s[i][j] = 0.f;
#pragma unroll 4
        for (int d = 0; d < Dc; d++) {
            float a[4], bb[4];
#pragma unroll
            for (int i = 0; i < 4; i++) a[i]  = Qs[(ty * 4 + i) * QP + d];
#pragma unroll
            for (int j = 0; j < 4; j++) bb[j] = Ks[(tx * 4 + j) * QP + d];
#pragma unroll
            for (int i = 0; i < 4; i++)
#pragma unroll
                for (int j = 0; j < 4; j++)
                    s[i][j] = fmaf(a[i], bb[j], s[i][j]);
        }

#pragma unroll
        for (int i = 0; i < 4; i++) {
            int r = ty * 4 + i;
            float sv[4];
            float mb = -1e38f;
#pragma unroll
            for (int j = 0; j < 4; j++) {
                float v = s[i][j] * SCALEc;
                if (diag && (tx * 4 + j) > r) v = -1e30f;
                sv[j] = v;
                mb = fmaxf(mb, v);
            }
#pragma unroll
            for (int o = 1; o < 16; o <<= 1)
                mb = fmaxf(mb, __shfl_xor_sync(0xffffffffu, mb, o));
            float mn = fmaxf(m[i], mb);
            float alpha = __expf(m[i] - mn);
            m[i] = mn;
            float ls = 0.f;
#pragma unroll
            for (int j = 0; j < 4; j++) {
                float p = __expf(sv[j] - mn);
                Ps[r * PP + tx * 4 + j] = p;
                ls += p;
            }
#pragma unroll
            for (int o = 1; o < 16; o <<= 1)
                ls += __shfl_xor_sync(0xffffffffu, ls, o);
            l[i] = l[i] * alpha + ls;
#pragma unroll
            for (int jj = 0; jj < 8; jj++) acc[i][jj] *= alpha;
        }
        __syncthreads();

        const float* vp = vg + (size_t)jb * 64 * Dc;
        for (int idx = t * 4; idx < 64 * 128; idx += 1024) {
            int r = idx >> 7, c = idx & 127;
            *(float4*)(Vs + r * 128 + c) = *(const float4*)(vp + r * Dc + c);
        }
        __syncthreads();

#pragma unroll 2
        for (int c = 0; c < 64; c++) {
            float pv[4];
#pragma unroll
            for (int i = 0; i < 4; i++) pv[i] = Ps[(ty * 4 + i) * PP + c];
            float4 v0 = *(const float4*)(Vs + c * 128 + tx * 8);
            float4 v1 = *(const float4*)(Vs + c * 128 + tx * 8 + 4);
#pragma unroll
            for (int i = 0; i < 4; i++) {
                acc[i][0] = fmaf(pv[i], v0.x, acc[i][0]);
                acc[i][1] = fmaf(pv[i], v0.y, acc[i][1]);
                acc[i][2] = fmaf(pv[i], v0.z, acc[i][2]);
                acc[i][3] = fmaf(pv[i], v0.w, acc[i][3]);
                acc[i][4] = fmaf(pv[i], v1.x, acc[i][4]);
                acc[i][5] = fmaf(pv[i], v1.y, acc[i][5]);
                acc[i][6] = fmaf(pv[i], v1.z, acc[i][6]);
                acc[i][7] = fmaf(pv[i], v1.w, acc[i][7]);
            }
        }
        __syncthreads();
    }

#pragma unroll
    for (int i = 0; i < 4; i++) {
        float inv = 1.0f / l[i];
        size_t row = (size_t)b * Sc + ib * 64 + ty * 4 + i;
        float* op = g_attn + row * 2048 + h * 128 + tx * 8;
        *(float4*)(op)     = make_float4(acc[i][0] * inv, acc[i][1] * inv,
                                         acc[i][2] * inv, acc[i][3] * inv);
        *(float4*)(op + 4) = make_float4(acc[i][4] * inv, acc[i][5] * inv,
                                         acc[i][6] * inv, acc[i][7] * inv);
    }
}

// ---------------- launch ----------------
extern "C" void kernel_launch(void* const* d_in, const int* in_sizes, int n_in,
                              void* d_out, int out_size)
{
    const float* hidden = (const float*)d_in[0];
    const float* cosb   = (const float*)d_in[1];
    const float* sinb   = (const float*)d_in[2];
    const float* Wq     = (const float*)d_in[3];
    const float* Wk     = (const float*)d_in[4];
    const float* Wv     = (const float*)d_in[5];
    const float* Wo     = (const float*)d_in[6];
    float* out = (float*)d_out;

    float *qkv, *q, *k, *qblk, *kblk, *attn, *wt, *wot;
    cudaGetSymbolAddress((void**)&qkv,  g_qkv);
    cudaGetSymbolAddress((void**)&q,    g_q);
    cudaGetSymbolAddress((void**)&k,    g_k);
    cudaGetSymbolAddress((void**)&qblk, g_qblk);
    cudaGetSymbolAddress((void**)&kblk, g_kblk);
    cudaGetSymbolAddress((void**)&attn, g_attn);
    cudaGetSymbolAddress((void**)&wt,   g_wt);
    cudaGetSymbolAddress((void**)&wot,  g_wot);

    // 0. transpose weights into [N][K] layout
    transpose_k<<<dim3(64, 64), dim3(32, 8)>>>(Wq, wt,                       2048, 2048);
    transpose_k<<<dim3(16, 64), dim3(32, 8)>>>(Wk, wt + (size_t)2048 * 2048, 2048, 512);
    transpose_k<<<dim3(16, 64), dim3(32, 8)>>>(Wv, wt + (size_t)2560 * 2048, 2048, 512);
    transpose_k<<<dim3(64, 64), dim3(32, 8)>>>(Wo, wot,                      2048, 2048);

    cudaFuncSetAttribute(gemm_mma, cudaFuncAttributeMaxDynamicSharedMemorySize, GEMM_SMEM);

    // 1. fused QKV projection (tf32 tensor cores, 3xTF32): (4096 x 2048) @ (2048 x 3072)
    gemm_mma<<<dim3(24, 32), 256, GEMM_SMEM>>>(hidden, wt, qkv, 3072, 2048);

    // 2. RoPE + layout change
    rope_kernel<<<dim3(Sc, Bc), 256>>>(qkv, cosb, sinb);

    // 3. block means
    blockmean_kernel<<<dim3(NBc, Hc,   Bc), 128>>>(q, qblk, Hc);
    blockmean_kernel<<<dim3(NBc, HKVc, Bc), 128>>>(k, kblk, HKVc);

    // 4. gate bitmask
    mask_kernel<<<Bc * Hc, 1024>>>();

    // 5. block-sparse flash attention
    int smem = (64 * QP * 2 + 64 * PP) * (int)sizeof(float);   // 82688 B
    cudaFuncSetAttribute(flash_kernel, cudaFuncAttributeMaxDynamicSharedMemorySize, smem);
    flash_kernel<<<dim3(NBc, Hc, Bc), 256, smem>>>();

    // 6. output projection: (4096 x 2048) @ (2048 x 2048)
    gemm_mma<<<dim3(16, 32), 256, GEMM_SMEM>>>(attn, wot, out, 2048, 2048);
}

// round 5
// speedup vs baseline: 1.6989x; 1.3395x over previous
#include <cuda_runtime.h>
#include <cuda_fp16.h>
#include <math.h>
#include <cstdint>

// Problem constants
#define Bc   2
#define Sc   2048
#define HIDc 2048
#define Hc   16
#define HKVc 4
#define Dc   128
#define BSc  64
#define NBc  32
#define SCALEc 0.08838834764831845f   // 1/sqrt(128)

// ---------------- scratch (device globals; no allocation allowed) ----------------
__device__ float    g_qkv[(size_t)4096 * 3072];          // hidden @ [Wq|Wk|Wv]
__device__ float    g_q  [(size_t)Bc * Hc   * Sc * Dc];  // roped, (B,H,S,D)
__device__ float    g_k  [(size_t)Bc * HKVc * Sc * Dc];  // roped, (B,HKV,S,D)
__device__ float    g_v  [(size_t)Bc * HKVc * Sc * Dc];
__device__ float    g_qblk[Bc * Hc   * NBc * Dc];
__device__ float    g_kblk[Bc * HKVc * NBc * Dc];
__device__ unsigned g_mask[Bc * Hc * NBc];               // bit j of row i: block (i,j) active
__device__ float    g_attn[(size_t)4096 * 2048];         // (B,S,H*D)

// fp16 limb arrays (value = hi + lo, each operand pre-split once)
__device__ __half g_hh [(size_t)4096 * 2048];   // hidden hi
__device__ __half g_hl [(size_t)4096 * 2048];   // hidden lo
__device__ __half g_wth[(size_t)3072 * 2048];   // [Wq^T;Wk^T;Wv^T] hi  (rows=N, cols=K)
__device__ __half g_wtl[(size_t)3072 * 2048];
__device__ __half g_woth[(size_t)2048 * 2048];  // Wo^T hi
__device__ __half g_wotl[(size_t)2048 * 2048];
__device__ __half g_ath[(size_t)4096 * 2048];   // attn hi
__device__ __half g_atl[(size_t)4096 * 2048];

// ======================= helpers =======================
__device__ __forceinline__ uint32_t smem_u32(const void* p) {
    uint32_t a;
    asm("{ .reg .u64 t; cvta.to.shared.u64 t, %1; cvt.u32.u64 %0, t; }" : "=r"(a) : "l"(p));
    return a;
}
__device__ __forceinline__ void ldm4(uint32_t addr, uint32_t* r) {
    asm volatile("ldmatrix.sync.aligned.m8n8.x4.shared.b16 {%0,%1,%2,%3}, [%4];"
        : "=r"(r[0]), "=r"(r[1]), "=r"(r[2]), "=r"(r[3]) : "r"(addr));
}
#define MMA_F16(d, a, b) \
    asm volatile("mma.sync.aligned.m16n8k16.row.col.f32.f16.f16.f32 " \
        "{%0,%1,%2,%3}, {%4,%5,%6,%7}, {%8,%9}, {%0,%1,%2,%3};" \
        : "+f"((d)[0]), "+f"((d)[1]), "+f"((d)[2]), "+f"((d)[3]) \
        : "r"((a)[0]), "r"((a)[1]), "r"((a)[2]), "r"((a)[3]), \
          "r"((b)[0]), "r"((b)[1]))
#define CP_ASYNC16(dst, src) \
    asm volatile("cp.async.cg.shared.global [%0], [%1], 16;" :: "r"(dst), "l"(src))
#define CP_COMMIT()  asm volatile("cp.async.commit_group;" ::: "memory")
#define CP_WAIT1()   asm volatile("cp.async.wait_group 1;" ::: "memory")
#define CP_WAIT0()   asm volatile("cp.async.wait_group 0;" ::: "memory")

// ================== fp16x3 split GEMM: C[M,*] = (A) @ (Bt)^T ==================
// Operands pre-split into hi/lo half limbs in GMEM. CTA tile 128x128, K-chunk 32.
// smem tile: 128 rows x 40 halfs (80B rows; 20r mod 32 permutation -> ldmatrix
// phase conflict-free). Stage = Ah|Al|Bh|Bl. 2-stage cp.async pipeline.
#define KCH     32
#define TROW    40                         // halfs per smem row
#define TILE_B  (128 * TROW * 2)           // 10240 B
#define STAGE_B (4 * TILE_B)               // 40960 B
#define GEMM_SMEM (2 * STAGE_B)            // 81920 B

__global__ void __launch_bounds__(256, 2) gemm_h(
    const __half* __restrict__ Ahg, const __half* __restrict__ Alg,
    const __half* __restrict__ Bhg, const __half* __restrict__ Blg,
    float* __restrict__ C, int ldc, int K)
{
    extern __shared__ char smc[];
    const uint32_t sb = smem_u32(smc);
    const int tid = threadIdx.x;
    const int wid = tid >> 5, lane = tid & 31;
    const int wm = wid & 1, wn = wid >> 1;        // warp grid 2(m) x 4(n), tile 64x32
    const int g = lane >> 2, q = lane & 3;
    const int row0 = blockIdx.y * 128;
    const int col0 = blockIdx.x * 128;
    const __half* A0 = Ahg + (size_t)row0 * K;
    const __half* A1 = Alg + (size_t)row0 * K;
    const __half* B0 = Bhg + (size_t)col0 * K;
    const __half* B1 = Blg + (size_t)col0 * K;

    float acc[4][4][4];
#pragma unroll
    for (int t = 0; t < 4; t++)
#pragma unroll
        for (int u = 0; u < 4; u++)
#pragma unroll
            for (int r = 0; r < 4; r++) acc[t][u][r] = 0.f;

    // ldmatrix lane addressing: rows base+(lane&15), 16B col-half (lane>>4)
    const int lrow = lane & 15;
    const uint32_t lk = (uint32_t)(lane >> 4) * 16;   // bytes

    auto prefetch = [&](int kc, int s) {
        const int k0 = kc * KCH;
        const uint32_t st = sb + s * STAGE_B;
        const __half* gs[4] = {A0, A1, B0, B1};
#pragma unroll
        for (int t4 = 0; t4 < 4; t4++) {
#pragma unroll
            for (int j = 0; j < 2; j++) {
                int idx = tid + j * 256;          // 0..511
                int row = idx >> 2, seg = idx & 3;
                uint32_t dst = st + t4 * TILE_B + row * 80 + seg * 16;
                const __half* src = gs[t4] + (size_t)row * K + k0 + seg * 8;
                CP_ASYNC16(dst, src);
            }
        }
    };

    auto compute = [&](int s) {
        const uint32_t st = sb + s * STAGE_B;
#pragma unroll
        for (int kb = 0; kb < 2; kb++) {
            const uint32_t ko = kb * 32 + lk;
            uint32_t a[4][4], b[4][2], b2[4][2], r[4];
            // B hi frags (2 ldmatrix.x4 -> 4 u tiles)
#pragma unroll
            for (int p = 0; p < 2; p++) {
                ldm4(st + 2 * TILE_B + (wn * 32 + p * 16 + lrow) * 80 + ko, r);
                b[2 * p][0] = r[0]; b[2 * p + 1][0] = r[1];
                b[2 * p][1] = r[2]; b[2 * p + 1][1] = r[3];
            }
            // A hi frags
#pragma unroll
            for (int t = 0; t < 4; t++)
                ldm4(st + (wm * 64 + t * 16 + lrow) * 80 + ko, a[t]);
#pragma unroll
            for (int t = 0; t < 4; t++)
#pragma unroll
                for (int u = 0; u < 4; u++) MMA_F16(acc[t][u], a[t], b[u]);
            // B lo frags
#pragma unroll
            for (int p = 0; p < 2; p++) {
                ldm4(st + 3 * TILE_B + (wn * 32 + p * 16 + lrow) * 80 + ko, r);
                b2[2 * p][0] = r[0]; b2[2 * p + 1][0] = r[1];
                b2[2 * p][1] = r[2]; b2[2 * p + 1][1] = r[3];
            }
#pragma unroll
            for (int t = 0; t < 4; t++)
#pragma unroll
                for (int u = 0; u < 4; u++) MMA_F16(acc[t][u], a[t], b2[u]);
            // A lo frags (overwrite hi)
#pragma unroll
            for (int t = 0; t < 4; t++)
                ldm4(st + TILE_B + (wm * 64 + t * 16 + lrow) * 80 + ko, a[t]);
#pragma unroll
            for (int t = 0; t < 4; t++)
#pragma unroll
                for (int u = 0; u < 4; u++) MMA_F16(acc[t][u], a[t], b[u]);
        }
    };

    const int nch = K / KCH;    // 64
    prefetch(0, 0); CP_COMMIT();
    prefetch(1, 1); CP_COMMIT();
    for (int kc = 0; kc < nch; kc++) {
        int s = kc & 1;
        if (kc + 1 < nch) { CP_WAIT1(); } else { CP_WAIT0(); }
        __syncthreads();
        compute(s);
        __syncthreads();
        if (kc + 2 < nch) prefetch(kc + 2, s);
        CP_COMMIT();
    }

    // epilogue: regs -> C (f32)
#pragma unroll
    for (int t = 0; t < 4; t++) {
        int r = row0 + wm * 64 + t * 16 + g;
#pragma unroll
        for (int u = 0; u < 4; u++) {
            int c = col0 + wn * 32 + u * 8 + q * 2;
            *(float2*)(C + (size_t)r * ldc + c)       = make_float2(acc[t][u][0], acc[t][u][1]);
            *(float2*)(C + (size_t)(r + 8) * ldc + c) = make_float2(acc[t][u][2], acc[t][u][3]);
        }
    }
}

// ---------------- transpose + fp16 limb split: in[Kdim][Ndim] -> hi/lo[Ndim][Kdim] ----------------
__global__ __launch_bounds__(256) void transpose_split(
    const float* __restrict__ in, __half* __restrict__ oh, __half* __restrict__ ol,
    int Kdim, int Ndim)
{
    __shared__ float t[32][33];
    int bx = blockIdx.x * 32, by = blockIdx.y * 32;   // bx: n, by: k
    int x = threadIdx.x, y = threadIdx.y;             // 32 x 8
#pragma unroll
    for (int i = 0; i < 32; i += 8)
        t[y + i][x] = in[(size_t)(by + y + i) * Ndim + bx + x];
    __syncthreads();
#pragma unroll
    for (int i = 0; i < 32; i += 8) {
        float v = t[x][y + i];
        __half h = __float2half_rn(v);
        __half l = __float2half_rn(v - __half2float(h));
        size_t o = (size_t)(bx + y + i) * Kdim + by + x;
        oh[o] = h; ol[o] = l;
    }
}

// ---------------- fp16 limb split (no transpose) ----------------
__global__ __launch_bounds__(256) void split_kernel(
    const float* __restrict__ in, __half* __restrict__ oh, __half* __restrict__ ol, int n)
{
    int i = (blockIdx.x * 256 + threadIdx.x) * 4;
    if (i >= n) return;
    float4 v = *(const float4*)(in + i);
    __half hx = __float2half_rn(v.x), hy = __float2half_rn(v.y);
    __half hz = __float2half_rn(v.z), hw = __float2half_rn(v.w);
    __half lx = __float2half_rn(v.x - __half2float(hx));
    __half ly = __float2half_rn(v.y - __half2float(hy));
    __half lz = __float2half_rn(v.z - __half2float(hz));
    __half lw = __float2half_rn(v.w - __half2float(hw));
    *(__half2*)(oh + i)     = __halves2half2(hx, hy);
    *(__half2*)(oh + i + 2) = __halves2half2(hz, hw);
    *(__half2*)(ol + i)     = __halves2half2(lx, ly);
    *(__half2*)(ol + i + 2) = __halves2half2(lz, lw);
}

// ---------------- RoPE + reshape: qkv(B,S,3072) -> q(B,H,S,D), k/v(B,HKV,S,D) ----------------
__global__ void rope_kernel(const float* __restrict__ qkv,
                            const float* __restrict__ cosb,
                            const float* __restrict__ sinb)
{
    int s = blockIdx.x, b = blockIdx.y;
    const float* row = qkv + (size_t)(b * Sc + s) * 3072;
    const float* cr  = cosb + (size_t)(b * Sc + s) * Dc;
    const float* sr  = sinb + (size_t)(b * Sc + s) * Dc;
    int t = threadIdx.x;

    for (int p = t; p < Hc * 64; p += 256) {            // q pairs
        int h = p >> 6, d = p & 63;
        float x1 = row[h * 128 + d], x2 = row[h * 128 + d + 64];
        float* out = g_q + ((size_t)(b * Hc + h) * Sc + s) * Dc;
        out[d]      = x1 * cr[d]      - x2 * sr[d];
        out[d + 64] = x2 * cr[d + 64] + x1 * sr[d + 64];
    }
    for (int p = t; p < HKVc * 64; p += 256) {          // k pairs
        int h = p >> 6, d = p & 63;
        float x1 = row[2048 + h * 128 + d], x2 = row[2048 + h * 128 + d + 64];
        float* out = g_k + ((size_t)(b * HKVc + h) * Sc + s) * Dc;
        out[d]      = x1 * cr[d]      - x2 * sr[d];
        out[d + 64] = x2 * cr[d + 64] + x1 * sr[d + 64];
    }
    for (int p = t; p < HKVc * Dc; p += 256) {          // v copy
        int h = p >> 7, d = p & 127;
        g_v[((size_t)(b * HKVc + h) * Sc + s) * Dc + d] = row[2560 + h * 128 + d];
    }
}

// ---------------- block means over BS=64 rows ----------------
__global__ void blockmean_kernel(const float* __restrict__ x, float* __restrict__ out, int HH)
{
    int i = blockIdx.x, h = blockIdx.y, b = blockIdx.z, d = threadIdx.x;
    const float* base = x + ((size_t)(b * HH + h) * Sc + i * BSc) * Dc + d;
    float sum = 0.f;
#pragma unroll
    for (int r = 0; r < BSc; r++) sum += base[(size_t)r * Dc];
    out[((size_t)(b * HH + h) * NBc + i) * Dc + d] = sum * (1.0f / 64.0f);
}

// ---------------- gate mask: sigmoid(logit)>=0.5 <=> logit>=0; pack row bitmask ----------------
__global__ __launch_bounds__(1024) void mask_kernel()
{
    int bh = blockIdx.x;                 // b*H + h
    int b = bh / Hc, h = bh % Hc;
    int t = threadIdx.x;
    int i = t >> 5, j = t & 31;
    const float* qb = g_qblk + ((size_t)bh * NBc + i) * Dc;
    const float* kb = g_kblk + ((size_t)(b * HKVc + (h >> 2)) * NBc + j) * Dc;
    float dot = 0.f;
#pragma unroll 8
    for (int d = 0; d < Dc; d++) dot = fmaf(qb[d], kb[d], dot);
    bool hard = (dot * SCALEc >= 0.0f) || (i == j);
    hard = hard && (j <= i);
    unsigned bits = __ballot_sync(0xffffffffu, hard);
    if (j == 0) g_mask[(size_t)bh * NBc + i] = bits;
}

// ---------------- block-sparse flash attention (fp32) ----------------
#define QP 129   // K/Q smem row stride
#define PP 65    // P smem row stride
__global__ __launch_bounds__(256) void flash_kernel()
{
    extern __shared__ float smf[];
    float* Qs = smf;                // [64][QP]
    float* Ks = Qs + 64 * QP;       // [64][QP]; aliased as Vs [64][128]
    float* Ps = Ks + 64 * QP;       // [64][PP]
    float* Vs = Ks;

    int ib = blockIdx.x, h = blockIdx.y, b = blockIdx.z;
    int t = threadIdx.x;
    int ty = t >> 4, tx = t & 15;

    const float* qg = g_q + ((size_t)(b * Hc + h) * Sc + ib * 64) * Dc;
    const float* kg = g_k + ((size_t)(b * HKVc + (h >> 2)) * Sc) * Dc;
    const float* vg = g_v + ((size_t)(b * HKVc + (h >> 2)) * Sc) * Dc;
    const unsigned maskrow = g_mask[(size_t)(b * Hc + h) * NBc + ib];

    for (int idx = t * 4; idx < 64 * 128; idx += 1024) {
        int r = idx >> 7, c = idx & 127;
        float4 v4 = *(const float4*)(qg + r * Dc + c);
        float* dst = Qs + r * QP + c;
        dst[0] = v4.x; dst[1] = v4.y; dst[2] = v4.z; dst[3] = v4.w;
    }

    float m[4], l[4], acc[4][8];
#pragma unroll
    for (int i = 0; i < 4; i++) {
        m[i] = -1e38f; l[i] = 0.f;
#pragma unroll
        for (int j = 0; j < 8; j++) acc[i][j] = 0.f;
    }
    __syncthreads();

    for (int jb = 0; jb <= ib; jb++) {
        if (!((maskrow >> jb) & 1u)) continue;
        const bool diag = (jb == ib);

        const float* kp = kg + (size_t)jb * 64 * Dc;
        for (int idx = t * 4; idx < 64 * 128; idx += 1024) {
            int r = idx >> 7, c = idx & 127;
            float4 v4 = *(const float4*)(kp + r * Dc + c);
            float* dst = Ks + r * QP + c;
            dst[0] = v4.x; dst[1] = v4.y; dst[2] = v4.z; dst[3] = v4.w;
        }
        __syncthreads();

        float s[4][4];
#pragma unroll
        for (int i = 0; i < 4; i++)
#pragma unroll
            for (int j = 0; j < 4; j++) s[i][j] = 0.f;
#pragma unroll 4
        for (int d = 0; d < Dc; d++) {
            float a[4], bb[4];
#pragma unroll
            for (int i = 0; i < 4; i++) a[i]  = Qs[(ty * 4 + i) * QP + d];
#pragma unroll
            for (int j = 0; j < 4; j++) bb[j] = Ks[(tx * 4 + j) * QP + d];
#pragma unroll
            for (int i = 0; i < 4; i++)
#pragma unroll
                for (int j = 0; j < 4; j++)
                    s[i][j] = fmaf(a[i], bb[j], s[i][j]);
        }

#pragma unroll
        for (int i = 0; i < 4; i++) {
            int r = ty * 4 + i;
            float sv[4];
            float mb = -1e38f;
#pragma unroll
            for (int j = 0; j < 4; j++) {
                float v = s[i][j] * SCALEc;
                if (diag && (tx * 4 + j) > r) v = -1e30f;
                sv[j] = v;
                mb = fmaxf(mb, v);
            }
#pragma unroll
            for (int o = 1; o < 16; o <<= 1)
                mb = fmaxf(mb, __shfl_xor_sync(0xffffffffu, mb, o));
            float mn = fmaxf(m[i], mb);
            float alpha = __expf(m[i] - mn);
            m[i] = mn;
            float ls = 0.f;
#pragma unroll
            for (int j = 0; j < 4; j++) {
                float p = __expf(sv[j] - mn);
                Ps[r * PP + tx * 4 + j] = p;
                ls += p;
            }
#pragma unroll
            for (int o = 1; o < 16; o <<= 1)
                ls += __shfl_xor_sync(0xffffffffu, ls, o);
            l[i] = l[i] * alpha + ls;
#pragma unroll
            for (int jj = 0; jj < 8; jj++) acc[i][jj] *= alpha;
        }
        __syncthreads();

        const float* vp = vg + (size_t)jb * 64 * Dc;
        for (int idx = t * 4; idx < 64 * 128; idx += 1024) {
            int r = idx >> 7, c = idx & 127;
            *(float4*)(Vs + r * 128 + c) = *(const float4*)(vp + r * Dc + c);
        }
        __syncthreads();

#pragma unroll 2
        for (int c = 0; c < 64; c++) {
            float pv[4];
#pragma unroll
            for (int i = 0; i < 4; i++) pv[i] = Ps[(ty * 4 + i) * PP + c];
            float4 v0 = *(const float4*)(Vs + c * 128 + tx * 8);
            float4 v1 = *(const float4*)(Vs + c * 128 + tx * 8 + 4);
#pragma unroll
            for (int i = 0; i < 4; i++) {
                acc[i][0] = fmaf(pv[i], v0.x, acc[i][0]);
                acc[i][1] = fmaf(pv[i], v0.y, acc[i][1]);
                acc[i][2] = fmaf(pv[i], v0.z, acc[i][2]);
                acc[i][3] = fmaf(pv[i], v0.w, acc[i][3]);
                acc[i][4] = fmaf(pv[i], v1.x, acc[i][4]);
                acc[i][5] = fmaf(pv[i], v1.y, acc[i][5]);
                acc[i][6] = fmaf(pv[i], v1.z, acc[i][6]);
                acc[i][7] = fmaf(pv[i], v1.w, acc[i][7]);
            }
        }
        __syncthreads();
    }

#pragma unroll
    for (int i = 0; i < 4; i++) {
        float inv = 1.0f / l[i];
        size_t row = (size_t)b * Sc + ib * 64 + ty * 4 + i;
        float* op = g_attn + row * 2048 + h * 128 + tx * 8;
        *(float4*)(op)     = make_float4(acc[i][0] * inv, acc[i][1] * inv,
                                         acc[i][2] * inv, acc[i][3] * inv);
        *(float4*)(op + 4) = make_float4(acc[i][4] * inv, acc[i][5] * inv,
                                         acc[i][6] * inv, acc[i][7] * inv);
    }
}

// ---------------- launch ----------------
extern "C" void kernel_launch(void* const* d_in, const int* in_sizes, int n_in,
                              void* d_out, int out_size)
{
    const float* hidden = (const float*)d_in[0];
    const float* cosb   = (const float*)d_in[1];
    const float* sinb   = (const float*)d_in[2];
    const float* Wq     = (const float*)d_in[3];
    const float* Wk     = (const float*)d_in[4];
    const float* Wv     = (const float*)d_in[5];
    const float* Wo     = (const float*)d_in[6];
    float* out = (float*)d_out;

    float *qkv, *q, *k, *qblk, *kblk, *attn;
    __half *hh, *hl, *wth, *wtl, *woth, *wotl, *ath, *atl;
    cudaGetSymbolAddress((void**)&qkv,  g_qkv);
    cudaGetSymbolAddress((void**)&q,    g_q);
    cudaGetSymbolAddress((void**)&k,    g_k);
    cudaGetSymbolAddress((void**)&qblk, g_qblk);
    cudaGetSymbolAddress((void**)&kblk, g_kblk);
    cudaGetSymbolAddress((void**)&attn, g_attn);
    cudaGetSymbolAddress((void**)&hh,   g_hh);
    cudaGetSymbolAddress((void**)&hl,   g_hl);
    cudaGetSymbolAddress((void**)&wth,  g_wth);
    cudaGetSymbolAddress((void**)&wtl,  g_wtl);
    cudaGetSymbolAddress((void**)&woth, g_woth);
    cudaGetSymbolAddress((void**)&wotl, g_wotl);
    cudaGetSymbolAddress((void**)&ath,  g_ath);
    cudaGetSymbolAddress((void**)&atl,  g_atl);

    // 0. weights -> transposed fp16 limbs; hidden -> fp16 limbs
    transpose_split<<<dim3(64, 64), dim3(32, 8)>>>(Wq, wth, wtl, 2048, 2048);
    transpose_split<<<dim3(16, 64), dim3(32, 8)>>>(Wk, wth + (size_t)2048 * 2048,
                                                       wtl + (size_t)2048 * 2048, 2048, 512);
    transpose_split<<<dim3(16, 64), dim3(32, 8)>>>(Wv, wth + (size_t)2560 * 2048,
                                                       wtl + (size_t)2560 * 2048, 2048, 512);
    transpose_split<<<dim3(64, 64), dim3(32, 8)>>>(Wo, woth, wotl, 2048, 2048);
    split_kernel<<<8192, 256>>>(hidden, hh, hl, 4096 * 2048);

    cudaFuncSetAttribute(gemm_h, cudaFuncAttributeMaxDynamicSharedMemorySize, GEMM_SMEM);

    // 1. fused QKV projection (fp16x3 tensor cores): (4096 x 2048) @ (2048 x 3072)
    gemm_h<<<dim3(24, 32), 256, GEMM_SMEM>>>(hh, hl, wth, wtl, qkv, 3072, 2048);

    // 2. RoPE + layout change
    rope_kernel<<<dim3(Sc, Bc), 256>>>(qkv, cosb, sinb);

    // 3. block means
    blockmean_kernel<<<dim3(NBc, Hc,   Bc), 128>>>(q, qblk, Hc);
    blockmean_kernel<<<dim3(NBc, HKVc, Bc), 128>>>(k, kblk, HKVc);

    // 4. gate bitmask
    mask_kernel<<<Bc * Hc, 1024>>>();

    // 5. block-sparse flash attention
    int smem = (64 * QP * 2 + 64 * PP) * (int)sizeof(float);   // 82688 B
    cudaFuncSetAttribute(flash_kernel, cudaFuncAttributeMaxDynamicSharedMemorySize, smem);
    flash_kernel<<<dim3(NBc, Hc, Bc), 256, smem>>>();

    // 6. attn -> fp16 limbs; output projection: (4096 x 2048) @ (2048 x 2048)
    split_kernel<<<8192, 256>>>(attn, ath, atl, 4096 * 2048);
    gemm_h<<<dim3(16, 32), 256, GEMM_SMEM>>>(ath, atl, woth, wotl, out, 2048, 2048);
}